// round 1
// baseline (speedup 1.0000x reference)
#include <cuda_runtime.h>
#include <cstdint>

// Problem constants
#define BB 8
#define LL 4096
#define DD 768
#define NCHUNK 64          // L split into 64 chunks of 64 rows
#define ROWS_PER_CHUNK (LL / NCHUNK)   // 64

// Scratch (device globals; no allocation allowed)
__device__ __align__(16) float g_part[BB * NCHUNK * DD];  // partial column sums
__device__ __align__(16) float g_sum[BB * DD];            // full column sums
__device__ float g_coef[BB];                              // ||sum||^2 / (D^2 L^4)

// ---------------------------------------------------------------------------
// Kernel 1: partial column sums. grid (NCHUNK, BB), block 192 threads.
// Each thread owns one float4 column group (192 * 4 = 768) and sums 64 rows.
// Each block streams a contiguous 192 KB region -> fully coalesced, MLP high.
// ---------------------------------------------------------------------------
__global__ __launch_bounds__(192) void colsum_partial_kernel(const float* __restrict__ x) {
    const int c = blockIdx.x;   // chunk
    const int b = blockIdx.y;   // batch
    const int t = threadIdx.x;  // 0..191, float4 lane within row

    const float4* xp = reinterpret_cast<const float4*>(
        x + ((size_t)b * LL + (size_t)c * ROWS_PER_CHUNK) * DD) + t;

    float4 s = make_float4(0.f, 0.f, 0.f, 0.f);
#pragma unroll 8
    for (int i = 0; i < ROWS_PER_CHUNK; i++) {
        float4 v = xp[(size_t)i * (DD / 4)];
        s.x += v.x; s.y += v.y; s.z += v.z; s.w += v.w;
    }
    reinterpret_cast<float4*>(g_part)[((size_t)b * NCHUNK + c) * (DD / 4) + t] = s;
}

// ---------------------------------------------------------------------------
// Kernel 2: finish the reduction + compute coef[b]. grid BB, block 256.
// Deterministic (fixed summation order), tiny traffic (1.5 MB).
// ---------------------------------------------------------------------------
__global__ __launch_bounds__(256) void reduce_coef_kernel() {
    const int b = blockIdx.x;
    float sq = 0.f;
    for (int d = threadIdx.x; d < DD; d += 256) {
        float s = 0.f;
#pragma unroll 8
        for (int c = 0; c < NCHUNK; c++)
            s += g_part[((size_t)b * NCHUNK + c) * DD + d];
        g_sum[b * DD + d] = s;
        sq += s * s;
    }
    __shared__ float red[256];
    red[threadIdx.x] = sq;
    __syncthreads();
    for (int o = 128; o > 0; o >>= 1) {
        if (threadIdx.x < o) red[threadIdx.x] += red[threadIdx.x + o];
        __syncthreads();
    }
    if (threadIdx.x == 0) {
        // coef = ||sum||^2 / (D^2 * L^4)
        double denom = (double)DD * (double)DD
                     * (double)LL * (double)LL * (double)LL * (double)LL;
        g_coef[b] = (float)((double)red[0] / denom);
    }
}

// ---------------------------------------------------------------------------
// Kernel 3: out[b,l,:] = alpha[l] + (x[b,l]·sum_b)*coef[b] * x[b,l,:]
// 8 warps/block, one warp per row, 8 rows/block (all same b).
// x row (3 KB) loaded once into registers as 6 float4 per lane,
// reused for both the dot product and the final scale-write.
// ---------------------------------------------------------------------------
__global__ __launch_bounds__(256) void finalize_kernel(const float* __restrict__ x,
                                                       const float* __restrict__ alpha,
                                                       float* __restrict__ out) {
    __shared__ float4 smean[DD / 4];   // 192 float4 = sum_b row

    const int rowbase = blockIdx.x * 8;
    const int b = rowbase >> 12;       // 4096 rows per batch, 8 | 4096 -> same b

    if (threadIdx.x < DD / 4)
        smean[threadIdx.x] = reinterpret_cast<const float4*>(g_sum + b * DD)[threadIdx.x];
    __syncthreads();

    const int warp = threadIdx.x >> 5;
    const int lane = threadIdx.x & 31;
    const int row  = rowbase + warp;
    const int l    = row & (LL - 1);

    const float4* xp = reinterpret_cast<const float4*>(x + (size_t)row * DD);
    float4 v[6];
    float dot = 0.f;
#pragma unroll
    for (int i = 0; i < 6; i++) {
        v[i] = xp[lane + i * 32];
        float4 m = smean[lane + i * 32];
        dot += v[i].x * m.x + v[i].y * m.y + v[i].z * m.z + v[i].w * m.w;
    }
#pragma unroll
    for (int off = 16; off > 0; off >>= 1)
        dot += __shfl_xor_sync(0xFFFFFFFFu, dot, off);

    const float y2 = dot * g_coef[b];
    const float a  = alpha[l];

    float4* op = reinterpret_cast<float4*>(out + (size_t)row * DD);
#pragma unroll
    for (int i = 0; i < 6; i++) {
        float4 o;
        o.x = a + y2 * v[i].x;
        o.y = a + y2 * v[i].y;
        o.z = a + y2 * v[i].z;
        o.w = a + y2 * v[i].w;
        op[lane + i * 32] = o;
    }
}

extern "C" void kernel_launch(void* const* d_in, const int* in_sizes, int n_in,
                              void* d_out, int out_size) {
    const float* x     = (const float*)d_in[0];   // [8, 4096, 768] f32
    const float* alpha = (const float*)d_in[1];   // [4096, 1] f32
    float* out = (float*)d_out;                   // [8, 4096, 768] f32

    colsum_partial_kernel<<<dim3(NCHUNK, BB), 192>>>(x);
    reduce_coef_kernel<<<BB, 256>>>();
    finalize_kernel<<<(BB * LL) / 8, 256>>>(x, alpha, out);
}